// round 15
// baseline (speedup 1.0000x reference)
#include <cuda_runtime.h>
#include <cuda_fp16.h>
#include <cstdint>
#include <math.h>

#define B_  2048
#define H_  4
#define D_  4096
#define M_  8
#define DM_ 512

// ---------------- scratch + monotonic barrier ----------------
__device__ __align__(16) __half g_Yh[(size_t)B_ * D_];
__device__ __align__(16) __half g_Wh[(size_t)D_ * D_];
__device__ unsigned g_bar;   // monotonic across graph replays; never reset

// ---------------- helpers ----------------
__device__ __forceinline__ uint32_t smem_u32(const void* p) {
    uint32_t a;
    asm("{ .reg .u64 t; cvta.to.shared.u64 t, %1; cvt.u32.u64 %0, t; }" : "=r"(a) : "l"(p));
    return a;
}

#define CP_ASYNC16(dst, src) \
    asm volatile("cp.async.cg.shared.global [%0], [%1], 16;" :: "r"(dst), "l"(src))
#define CP_COMMIT()  asm volatile("cp.async.commit_group;" ::: "memory")
#define CP_WAIT1()   asm volatile("cp.async.wait_group 1;" ::: "memory")
#define CP_WAIT0()   asm volatile("cp.async.wait_group 0;" ::: "memory")

#define LDSM_X4(r, addr) \
    asm volatile("ldmatrix.sync.aligned.m8n8.x4.shared.b16 {%0,%1,%2,%3}, [%4];" \
                 : "=r"((r)[0]), "=r"((r)[1]), "=r"((r)[2]), "=r"((r)[3]) : "r"(addr))

__device__ __forceinline__ void mma_f16(float* d, const uint32_t* a, const uint32_t* b) {
    asm volatile(
        "mma.sync.aligned.m16n8k16.row.col.f32.f16.f16.f32 "
        "{%0,%1,%2,%3}, {%4,%5,%6,%7}, {%8,%9}, {%0,%1,%2,%3};"
        : "+f"(d[0]), "+f"(d[1]), "+f"(d[2]), "+f"(d[3])
        : "r"(a[0]), "r"(a[1]), "r"(a[2]), "r"(a[3]), "r"(b[0]), "r"(b[1]));
}

__device__ __forceinline__ float sigmoidf_(float v) {
    return __fdividef(1.0f, 1.0f + __expf(-v));
}

// ---------------- geometry ----------------
#define TM      128
#define TN      128
#define KC      64
#define NCHUNK  (D_ / KC)           // 64
#define SROW    72
#define STAGE_H (2 * 128 * SROW)    // 18432 halves
#define NSTAGE  3
#define SM_BYTES (NSTAGE * STAGE_H * 2)   // 110592 B -> occ 2
#define NTHR    128
#define NTILES  ((B_ / TM) * (D_ / TN))   // 512
#define NWORK   296                       // 148 SMs x occ 2 = full residency
#define NTHREADS_ALL (NWORK * NTHR)       // 37888

#define W_UNITS ((int)((long long)D_ * D_ / 8))   // 2097152 (8-float units)
#define Y_UNITS ((int)((long long)B_ * D_ / 8))   // 1048576

__global__ __launch_bounds__(NTHR, 2)
void mega_kernel(const float* __restrict__ Wsrc,
                 const float* __restrict__ x,
                 const float* __restrict__ lW,
                 const float* __restrict__ lb,
                 const float* __restrict__ bias,
                 float* __restrict__ out) {
    extern __shared__ __half sm[];
    const uint32_t smb = smem_u32(sm);

    const int tid  = threadIdx.x;
    const int bid  = blockIdx.x;
    const int gtid = bid * NTHR + tid;

    // ================= phase 0: conversion (all 37888 threads) ============
    // W fp32 -> fp16
    for (int u = gtid; u < W_UNITS; u += NTHREADS_ALL) {
        long long base = (long long)u * 8;
        float4 v0 = *(const float4*)(Wsrc + base);
        float4 v1 = *(const float4*)(Wsrc + base + 4);
        __half2 h[4];
        h[0] = __floats2half2_rn(v0.x, v0.y);
        h[1] = __floats2half2_rn(v0.z, v0.w);
        h[2] = __floats2half2_rn(v1.x, v1.y);
        h[3] = __floats2half2_rn(v1.z, v1.w);
        *(uint4*)(g_Wh + base) = *(uint4*)h;
    }
    // Y build
    for (int u = gtid; u < Y_UNITS; u += NTHREADS_ALL) {
        long long flat = (long long)u * 8;
        int c = (int)(flat % DM_);
        long long t = flat / DM_;
        int b = (int)(t % B_);
        int m = (int)(t / B_);

        float w0 = lW[m * H_ + 0], w1 = lW[m * H_ + 1];
        float w2 = lW[m * H_ + 2], w3 = lW[m * H_ + 3];
        float bb = lb[m];

        const float* xb = x + (long long)b * H_ * D_ + m * DM_ + c;
        __half2 hv[4];
#pragma unroll
        for (int q = 0; q < 2; q++) {
            float4 v0 = *(const float4*)(xb + 0ll * D_ + q * 4);
            float4 v1 = *(const float4*)(xb + 1ll * D_ + q * 4);
            float4 v2 = *(const float4*)(xb + 2ll * D_ + q * 4);
            float4 v3 = *(const float4*)(xb + 3ll * D_ + q * 4);
            float rx = fmaf(w0, v0.x, fmaf(w1, v1.x, fmaf(w2, v2.x, fmaf(w3, v3.x, bb))));
            float ry = fmaf(w0, v0.y, fmaf(w1, v1.y, fmaf(w2, v2.y, fmaf(w3, v3.y, bb))));
            float rz = fmaf(w0, v0.z, fmaf(w1, v1.z, fmaf(w2, v2.z, fmaf(w3, v3.z, bb))));
            float rw = fmaf(w0, v0.w, fmaf(w1, v1.w, fmaf(w2, v2.w, fmaf(w3, v3.w, bb))));
            hv[q * 2 + 0] = __floats2half2_rn(rx, ry);
            hv[q * 2 + 1] = __floats2half2_rn(rz, rw);
        }
        *(uint4*)(g_Yh + flat) = *(uint4*)hv;
    }

    // ================= grid barrier (monotonic, replay-safe) ==============
    __syncthreads();
    __threadfence();
    if (tid == 0) {
        unsigned old = atomicAdd(&g_bar, 1u);
        unsigned target = (old / NWORK + 1u) * NWORK;
        while (*((volatile unsigned*)&g_bar) < target) __nanosleep(64);
    }
    __syncthreads();
    __threadfence();

    // ================= phase 1: GEMM (R9 mainloop, static persistent) =====
    const int wid  = tid >> 5;
    const int lane = tid & 31;
    const int wm   = wid >> 1;
    const int wn   = wid & 1;

    uint32_t stage_base[NSTAGE];
#pragma unroll
    for (int s = 0; s < NSTAGE; s++) stage_base[s] = smb + (uint32_t)(s * STAGE_H) * 2;

    int a_off[4], b_off[4];
#pragma unroll
    for (int am = 0; am < 4; am++)
        a_off[am] = (wm * 64 + am * 16 + (lane & 15)) * SROW + ((lane >> 4) << 3);
    {
        const int seg = lane >> 3;
#pragma unroll
        for (int bn = 0; bn < 4; bn++)
            b_off[bn] = (128 + wn * 64 + bn * 16 + ((seg >> 1) << 3) + (lane & 7)) * SROW
                      + ((seg & 1) << 3);
    }

    const int lrow = tid >> 3;
    const int lc8  = tid & 7;

    for (int tile = bid; tile < NTILES; tile += NWORK) {
        const int bx = tile & 31;
        const int by = tile >> 5;
        const int row0 = by * TM;
        const int col0 = bx * TN;

        const __half* Ag = g_Yh + (long long)row0 * D_;
        const __half* Bg = g_Wh + (long long)col0 * D_;

        float d[4][8][4];
#pragma unroll
        for (int i = 0; i < 4; i++)
#pragma unroll
            for (int j = 0; j < 8; j++)
#pragma unroll
                for (int q = 0; q < 4; q++) d[i][j][q] = 0.0f;

        auto load_chunk = [&](int it, int s) {
            const int k0 = it * KC;
            const uint32_t aS = stage_base[s];
            const uint32_t bS = stage_base[s] + (uint32_t)(128 * SROW) * 2;
#pragma unroll
            for (int i = 0; i < 8; i++) {
                const int r = lrow + i * 16;
                CP_ASYNC16(aS + (uint32_t)(r * SROW + lc8 * 8) * 2,
                           Ag + (long long)r * D_ + k0 + lc8 * 8);
            }
#pragma unroll
            for (int i = 0; i < 8; i++) {
                const int r = lrow + i * 16;
                CP_ASYNC16(bS + (uint32_t)(r * SROW + lc8 * 8) * 2,
                           Bg + (long long)r * D_ + k0 + lc8 * 8);
            }
        };

        load_chunk(0, 0);
        CP_COMMIT();
        load_chunk(1, 1);
        CP_COMMIT();

        uint32_t a[2][4][4], b[2][4][4];

        int s = 0;
        for (int it = 0; it < NCHUNK; ++it) {
            CP_WAIT1();
            __syncthreads();

            if (it + 2 < NCHUNK) {
                int s2 = s + 2; if (s2 >= NSTAGE) s2 -= NSTAGE;
                load_chunk(it + 2, s2);
            }
            CP_COMMIT();

            const uint32_t base = stage_base[s];

#pragma unroll
            for (int am = 0; am < 4; am++)
                LDSM_X4(a[0][am], base + (uint32_t)a_off[am] * 2);
#pragma unroll
            for (int bn = 0; bn < 4; bn++)
                LDSM_X4(b[0][bn], base + (uint32_t)b_off[bn] * 2);

#pragma unroll
            for (int kk4 = 0; kk4 < 4; kk4++) {
                const int cur = kk4 & 1;
                if (kk4 < 3) {
                    const int kn = (kk4 + 1) * 16;
#pragma unroll
                    for (int am = 0; am < 4; am++)
                        LDSM_X4(a[cur ^ 1][am], base + (uint32_t)(a_off[am] + kn) * 2);
#pragma unroll
                    for (int bn = 0; bn < 4; bn++)
                        LDSM_X4(b[cur ^ 1][bn], base + (uint32_t)(b_off[bn] + kn) * 2);
                }
#pragma unroll
                for (int am = 0; am < 4; am++)
#pragma unroll
                    for (int j = 0; j < 8; j++)
                        mma_f16(d[am][j], a[cur][am], &b[cur][j >> 1][(j & 1) * 2]);
            }
            if (++s >= NSTAGE) s = 0;
        }

        CP_WAIT0();   // drain before smem reuse on next tile

        // epilogue: bias + sigmoid
        const int g = lane >> 2, t4 = lane & 3;
#pragma unroll
        for (int am = 0; am < 4; am++) {
            const int r0 = row0 + wm * 64 + am * 16 + g;
#pragma unroll
            for (int j = 0; j < 8; j++) {
                const int c = col0 + wn * 64 + j * 8 + t4 * 2;
                const float bxv = bias[c], byv = bias[c + 1];
                float2 o0, o1;
                o0.x = sigmoidf_(d[am][j][0] + bxv);
                o0.y = sigmoidf_(d[am][j][1] + byv);
                o1.x = sigmoidf_(d[am][j][2] + bxv);
                o1.y = sigmoidf_(d[am][j][3] + byv);
                *(float2*)(out + (long long)r0 * D_ + c)       = o0;
                *(float2*)(out + (long long)(r0 + 8) * D_ + c) = o1;
            }
        }
        __syncthreads();
    }
}

// ---------------- launch ----------------
extern "C" void kernel_launch(void* const* d_in, const int* in_sizes, int n_in,
                              void* d_out, int out_size) {
    const float* x  = (const float*)d_in[0];
    const float* lW = (const float*)d_in[1];
    const float* lb = (const float*)d_in[2];
    const float* pW = (const float*)d_in[3];
    const float* pb = (const float*)d_in[4];
    float* out = (float*)d_out;

    cudaFuncSetAttribute(mega_kernel,
                         cudaFuncAttributeMaxDynamicSharedMemorySize, SM_BYTES);
    mega_kernel<<<NWORK, NTHR, SM_BYTES>>>(pW, x, lW, lb, pb, out);
}

// round 16
// speedup vs baseline: 1.0533x; 1.0533x over previous
#include <cuda_runtime.h>
#include <cuda_fp16.h>
#include <cstdint>
#include <math.h>

#define B_  2048
#define H_  4
#define D_  4096
#define M_  8
#define DM_ 512

// ---------------- scratch (fp16 operands) ----------------
__device__ __align__(16) __half g_Yh[(size_t)B_ * D_];
__device__ __align__(16) __half g_Wh[(size_t)D_ * D_];

// ---------------- helpers ----------------
__device__ __forceinline__ uint32_t smem_u32(const void* p) {
    uint32_t a;
    asm("{ .reg .u64 t; cvta.to.shared.u64 t, %1; cvt.u32.u64 %0, t; }" : "=r"(a) : "l"(p));
    return a;
}

#define CP_ASYNC16(dst, src) \
    asm volatile("cp.async.cg.shared.global [%0], [%1], 16;" :: "r"(dst), "l"(src))
#define CP_COMMIT()  asm volatile("cp.async.commit_group;" ::: "memory")
#define CP_WAIT1()   asm volatile("cp.async.wait_group 1;" ::: "memory")

#define LDSM_X4(r, addr) \
    asm volatile("ldmatrix.sync.aligned.m8n8.x4.shared.b16 {%0,%1,%2,%3}, [%4];" \
                 : "=r"((r)[0]), "=r"((r)[1]), "=r"((r)[2]), "=r"((r)[3]) : "r"(addr))

__device__ __forceinline__ void mma_f16(float* d, const uint32_t* a, const uint32_t* b) {
    asm volatile(
        "mma.sync.aligned.m16n8k16.row.col.f32.f16.f16.f32 "
        "{%0,%1,%2,%3}, {%4,%5,%6,%7}, {%8,%9}, {%0,%1,%2,%3};"
        : "+f"(d[0]), "+f"(d[1]), "+f"(d[2]), "+f"(d[3])
        : "r"(a[0]), "r"(a[1]), "r"(a[2]), "r"(a[3]), "r"(b[0]), "r"(b[1]));
}

__device__ __forceinline__ float sigmoidf_(float v) {
    return __fdividef(1.0f, 1.0f + __expf(-v));
}

// ---------------- kernel 1: fused prologue (R9 version) -------------------
#define WBLK ((int)(((long long)D_ * D_ / 8) / 256))   // 8192 blocks
#define YBLK ((int)(((long long)B_ * D_ / 8) / 256))   // 4096 blocks

__global__ __launch_bounds__(256)
void prologue_kernel(const float* __restrict__ W,
                     const float* __restrict__ x,
                     const float* __restrict__ lW,
                     const float* __restrict__ lb) {
    const int bid = blockIdx.x;
    if (bid < WBLK) {
        long long base = ((long long)bid * 256 + threadIdx.x) * 8;
        float4 v0 = *(const float4*)(W + base);
        float4 v1 = *(const float4*)(W + base + 4);
        __half2 h[4];
        h[0] = __floats2half2_rn(v0.x, v0.y);
        h[1] = __floats2half2_rn(v0.z, v0.w);
        h[2] = __floats2half2_rn(v1.x, v1.y);
        h[3] = __floats2half2_rn(v1.z, v1.w);
        *(uint4*)(g_Wh + base) = *(uint4*)h;
    } else {
        long long flat = ((long long)(bid - WBLK) * 256 + threadIdx.x) * 8;
        int c = (int)(flat % DM_);
        long long t = flat / DM_;
        int b = (int)(t % B_);
        int m = (int)(t / B_);

        float w0 = lW[m * H_ + 0], w1 = lW[m * H_ + 1];
        float w2 = lW[m * H_ + 2], w3 = lW[m * H_ + 3];
        float bb = lb[m];

        const float* xb = x + (long long)b * H_ * D_ + m * DM_ + c;
        __half2 hv[4];
#pragma unroll
        for (int q = 0; q < 2; q++) {
            float4 v0 = *(const float4*)(xb + 0ll * D_ + q * 4);
            float4 v1 = *(const float4*)(xb + 1ll * D_ + q * 4);
            float4 v2 = *(const float4*)(xb + 2ll * D_ + q * 4);
            float4 v3 = *(const float4*)(xb + 3ll * D_ + q * 4);
            float rx = fmaf(w0, v0.x, fmaf(w1, v1.x, fmaf(w2, v2.x, fmaf(w3, v3.x, bb))));
            float ry = fmaf(w0, v0.y, fmaf(w1, v1.y, fmaf(w2, v2.y, fmaf(w3, v3.y, bb))));
            float rz = fmaf(w0, v0.z, fmaf(w1, v1.z, fmaf(w2, v2.z, fmaf(w3, v3.z, bb))));
            float rw = fmaf(w0, v0.w, fmaf(w1, v1.w, fmaf(w2, v2.w, fmaf(w3, v3.w, bb))));
            hv[q * 2 + 0] = __floats2half2_rn(rx, ry);
            hv[q * 2 + 1] = __floats2half2_rn(rz, rw);
        }
        *(uint4*)(g_Yh + flat) = *(uint4*)hv;
    }
}

// ---------------- kernel 2: fp16 mma GEMM, 64x128 CTA tiles ---------------
#define TM      64
#define TN      128
#define KC      64                        // halves per chunk (128 B rows)
#define NCHUNK  (D_ / KC)                 // 64
#define SROW    72                        // padded row stride in halves
#define A_ROWS  TM
#define B_ROWS  TN
#define STAGE_H ((A_ROWS + B_ROWS) * SROW)   // 13824 halves per stage
#define NSTAGE  3
#define SM_BYTES (NSTAGE * STAGE_H * 2)      // 82944 B -> occ 2
#define NTHR    128

__global__ __launch_bounds__(NTHR, 2)
void gemm_mma_kernel(const float* __restrict__ bias,
                     float* __restrict__ out) {
    extern __shared__ __half sm[];
    const uint32_t smb = smem_u32(sm);

    const int tid  = threadIdx.x;
    const int wid  = tid >> 5;
    const int lane = tid & 31;
    const int wm   = wid >> 1;     // 0..1 : 32-row slab
    const int wn   = wid & 1;      // 0..1 : 64-col slab

    const int row0 = blockIdx.y * TM;
    const int col0 = blockIdx.x * TN;

    const __half* Ag = g_Yh + (long long)row0 * D_;
    const __half* Bg = g_Wh + (long long)col0 * D_;

    uint32_t stage_base[NSTAGE];
#pragma unroll
    for (int s = 0; s < NSTAGE; s++) stage_base[s] = smb + (uint32_t)(s * STAGE_H) * 2;

    // ldmatrix offsets (halves; k added per step)
    int a_off[2], b_off[4];
#pragma unroll
    for (int am = 0; am < 2; am++)
        a_off[am] = (wm * 32 + am * 16 + (lane & 15)) * SROW + ((lane >> 4) << 3);
    {
        const int seg = lane >> 3;
#pragma unroll
        for (int bn = 0; bn < 4; bn++)
            b_off[bn] = (A_ROWS + wn * 64 + bn * 16 + ((seg >> 1) << 3) + (lane & 7)) * SROW
                      + ((seg & 1) << 3);
    }

    // gmem->smem: (64 A + 128 B) rows x 8 16B-chunks / 128 threads = 12 each
    const int lrow = tid >> 3;     // 0..15
    const int lc8  = tid & 7;

    float d[2][8][4];
#pragma unroll
    for (int i = 0; i < 2; i++)
#pragma unroll
        for (int j = 0; j < 8; j++)
#pragma unroll
            for (int q = 0; q < 4; q++) d[i][j][q] = 0.0f;

    auto load_chunk = [&](int it, int s) {
        const int k0 = it * KC;
        const uint32_t aS = stage_base[s];
        const uint32_t bS = stage_base[s] + (uint32_t)(A_ROWS * SROW) * 2;
#pragma unroll
        for (int i = 0; i < 4; i++) {              // A: 64 rows
            const int r = lrow + i * 16;
            CP_ASYNC16(aS + (uint32_t)(r * SROW + lc8 * 8) * 2,
                       Ag + (long long)r * D_ + k0 + lc8 * 8);
        }
#pragma unroll
        for (int i = 0; i < 8; i++) {              // B: 128 rows
            const int r = lrow + i * 16;
            CP_ASYNC16(bS + (uint32_t)(r * SROW + lc8 * 8) * 2,
                       Bg + (long long)r * D_ + k0 + lc8 * 8);
        }
    };

    load_chunk(0, 0);
    CP_COMMIT();
    load_chunk(1, 1);
    CP_COMMIT();

    uint32_t a[2][2][4], b[2][4][4];

    int s = 0;
    for (int it = 0; it < NCHUNK; ++it) {
        CP_WAIT1();
        __syncthreads();

        if (it + 2 < NCHUNK) {
            int s2 = s + 2; if (s2 >= NSTAGE) s2 -= NSTAGE;
            load_chunk(it + 2, s2);
        }
        CP_COMMIT();

        const uint32_t base = stage_base[s];

        // fragment prologue: kk=0 into buffer 0
#pragma unroll
        for (int am = 0; am < 2; am++)
            LDSM_X4(a[0][am], base + (uint32_t)a_off[am] * 2);
#pragma unroll
        for (int bn = 0; bn < 4; bn++)
            LDSM_X4(b[0][bn], base + (uint32_t)b_off[bn] * 2);

#pragma unroll
        for (int kk4 = 0; kk4 < 4; kk4++) {
            const int cur = kk4 & 1;
            if (kk4 < 3) {
                const int kn = (kk4 + 1) * 16;
#pragma unroll
                for (int am = 0; am < 2; am++)
                    LDSM_X4(a[cur ^ 1][am], base + (uint32_t)(a_off[am] + kn) * 2);
#pragma unroll
                for (int bn = 0; bn < 4; bn++)
                    LDSM_X4(b[cur ^ 1][bn], base + (uint32_t)(b_off[bn] + kn) * 2);
            }
#pragma unroll
            for (int am = 0; am < 2; am++)
#pragma unroll
                for (int j = 0; j < 8; j++)
                    mma_f16(d[am][j], a[cur][am], &b[cur][j >> 1][(j & 1) * 2]);
        }
        if (++s >= NSTAGE) s = 0;
    }

    // epilogue: bias + sigmoid
    const int g = lane >> 2, t4 = lane & 3;
#pragma unroll
    for (int am = 0; am < 2; am++) {
        const int r0 = row0 + wm * 32 + am * 16 + g;
#pragma unroll
        for (int j = 0; j < 8; j++) {
            const int c = col0 + wn * 64 + j * 8 + t4 * 2;
            const float bx = bias[c], by = bias[c + 1];
            float2 o0, o1;
            o0.x = sigmoidf_(d[am][j][0] + bx);
            o0.y = sigmoidf_(d[am][j][1] + by);
            o1.x = sigmoidf_(d[am][j][2] + bx);
            o1.y = sigmoidf_(d[am][j][3] + by);
            *(float2*)(out + (long long)r0 * D_ + c)       = o0;
            *(float2*)(out + (long long)(r0 + 8) * D_ + c) = o1;
        }
    }
}

// ---------------- launch ----------------
extern "C" void kernel_launch(void* const* d_in, const int* in_sizes, int n_in,
                              void* d_out, int out_size) {
    const float* x  = (const float*)d_in[0];
    const float* lW = (const float*)d_in[1];
    const float* lb = (const float*)d_in[2];
    const float* pW = (const float*)d_in[3];
    const float* pb = (const float*)d_in[4];
    float* out = (float*)d_out;

    prologue_kernel<<<WBLK + YBLK, 256>>>(pW, x, lW, lb);

    cudaFuncSetAttribute(gemm_mma_kernel,
                         cudaFuncAttributeMaxDynamicSharedMemorySize, SM_BYTES);
    dim3 grid(D_ / TN, B_ / TM);   // (32, 32) = 1024 CTAs
    gemm_mma_kernel<<<grid, NTHR, SM_BYTES>>>(pb, out);
}

// round 17
// speedup vs baseline: 1.0733x; 1.0190x over previous
#include <cuda_runtime.h>
#include <cuda_fp16.h>
#include <cstdint>
#include <math.h>

#define B_  2048
#define H_  4
#define D_  4096
#define M_  8
#define DM_ 512

// ---------------- scratch (fp16 operands) ----------------
__device__ __align__(16) __half g_Yh[(size_t)B_ * D_];
__device__ __align__(16) __half g_Wh[(size_t)D_ * D_];

// ---------------- helpers ----------------
__device__ __forceinline__ uint32_t smem_u32(const void* p) {
    uint32_t a;
    asm("{ .reg .u64 t; cvta.to.shared.u64 t, %1; cvt.u32.u64 %0, t; }" : "=r"(a) : "l"(p));
    return a;
}

#define CP_ASYNC16(dst, src) \
    asm volatile("cp.async.cg.shared.global [%0], [%1], 16;" :: "r"(dst), "l"(src))
#define CP_COMMIT()  asm volatile("cp.async.commit_group;" ::: "memory")
#define CP_WAIT1()   asm volatile("cp.async.wait_group 1;" ::: "memory")

#define LDSM_X4(r, addr) \
    asm volatile("ldmatrix.sync.aligned.m8n8.x4.shared.b16 {%0,%1,%2,%3}, [%4];" \
                 : "=r"((r)[0]), "=r"((r)[1]), "=r"((r)[2]), "=r"((r)[3]) : "r"(addr))

__device__ __forceinline__ void mma_f16(float* d, const uint32_t* a, const uint32_t* b) {
    asm volatile(
        "mma.sync.aligned.m16n8k16.row.col.f32.f16.f16.f32 "
        "{%0,%1,%2,%3}, {%4,%5,%6,%7}, {%8,%9}, {%0,%1,%2,%3};"
        : "+f"(d[0]), "+f"(d[1]), "+f"(d[2]), "+f"(d[3])
        : "r"(a[0]), "r"(a[1]), "r"(a[2]), "r"(a[3]), "r"(b[0]), "r"(b[1]));
}

__device__ __forceinline__ float sigmoidf_(float v) {
    return __fdividef(1.0f, 1.0f + __expf(-v));
}

// streaming (evict-first) float4 load
__device__ __forceinline__ float4 ldcs4(const float* p) {
    return __ldcs((const float4*)p);
}

// ---------------- kernel 1: fused prologue ----------------
#define WBLK ((int)(((long long)D_ * D_ / 8) / 256))   // 8192 blocks
#define YBLK ((int)(((long long)B_ * D_ / 8) / 256))   // 4096 blocks

__global__ __launch_bounds__(256)
void prologue_kernel(const float* __restrict__ W,
                     const float* __restrict__ x,
                     const float* __restrict__ lW,
                     const float* __restrict__ lb) {
    const int bid = blockIdx.x;
    if (bid < WBLK) {
        long long base = ((long long)bid * 256 + threadIdx.x) * 8;
        float4 v0 = ldcs4(W + base);
        float4 v1 = ldcs4(W + base + 4);
        __half2 h[4];
        h[0] = __floats2half2_rn(v0.x, v0.y);
        h[1] = __floats2half2_rn(v0.z, v0.w);
        h[2] = __floats2half2_rn(v1.x, v1.y);
        h[3] = __floats2half2_rn(v1.z, v1.w);
        *(uint4*)(g_Wh + base) = *(uint4*)h;
    } else {
        long long flat = ((long long)(bid - WBLK) * 256 + threadIdx.x) * 8;
        int c = (int)(flat % DM_);
        long long t = flat / DM_;
        int b = (int)(t % B_);
        int m = (int)(t / B_);

        float w0 = lW[m * H_ + 0], w1 = lW[m * H_ + 1];
        float w2 = lW[m * H_ + 2], w3 = lW[m * H_ + 3];
        float bb = lb[m];

        const float* xb = x + (long long)b * H_ * D_ + m * DM_ + c;
        __half2 hv[4];
#pragma unroll
        for (int q = 0; q < 2; q++) {
            float4 v0 = ldcs4(xb + 0ll * D_ + q * 4);
            float4 v1 = ldcs4(xb + 1ll * D_ + q * 4);
            float4 v2 = ldcs4(xb + 2ll * D_ + q * 4);
            float4 v3 = ldcs4(xb + 3ll * D_ + q * 4);
            float rx = fmaf(w0, v0.x, fmaf(w1, v1.x, fmaf(w2, v2.x, fmaf(w3, v3.x, bb))));
            float ry = fmaf(w0, v0.y, fmaf(w1, v1.y, fmaf(w2, v2.y, fmaf(w3, v3.y, bb))));
            float rz = fmaf(w0, v0.z, fmaf(w1, v1.z, fmaf(w2, v2.z, fmaf(w3, v3.z, bb))));
            float rw = fmaf(w0, v0.w, fmaf(w1, v1.w, fmaf(w2, v2.w, fmaf(w3, v3.w, bb))));
            hv[q * 2 + 0] = __floats2half2_rn(rx, ry);
            hv[q * 2 + 1] = __floats2half2_rn(rz, rw);
        }
        *(uint4*)(g_Yh + flat) = *(uint4*)hv;
    }
}

// ---------------- kernel 2: fp16 mma GEMM (R9 verbatim) -------------------
#define TM      128
#define TN      128
#define KC      64                  // halves per chunk (128 B rows)
#define NCHUNK  (D_ / KC)           // 64
#define SROW    72                  // padded row stride in halves (144 B)
#define STAGE_H (2 * 128 * SROW)    // halves per stage, A then B (18432)
#define NSTAGE  3
#define SM_BYTES (NSTAGE * STAGE_H * 2)   // 110592 B
#define NTHR    128

__global__ __launch_bounds__(NTHR, 2)
void gemm_mma_kernel(const float* __restrict__ bias,
                     float* __restrict__ out) {
    extern __shared__ __half sm[];
    const uint32_t smb = smem_u32(sm);

    const int tid  = threadIdx.x;
    const int wid  = tid >> 5;
    const int lane = tid & 31;
    const int wm   = wid >> 1;     // 0..1
    const int wn   = wid & 1;      // 0..1

    const int row0 = blockIdx.y * TM;
    const int col0 = blockIdx.x * TN;

    const __half* Ag = g_Yh + (long long)row0 * D_;
    const __half* Bg = g_Wh + (long long)col0 * D_;

    uint32_t stage_base[NSTAGE];
#pragma unroll
    for (int s = 0; s < NSTAGE; s++) stage_base[s] = smb + (uint32_t)(s * STAGE_H) * 2;

    int a_off[4], b_off[4];
#pragma unroll
    for (int am = 0; am < 4; am++)
        a_off[am] = (wm * 64 + am * 16 + (lane & 15)) * SROW + ((lane >> 4) << 3);
    {
        const int seg = lane >> 3;
#pragma unroll
        for (int bn = 0; bn < 4; bn++)
            b_off[bn] = (128 + wn * 64 + bn * 16 + ((seg >> 1) << 3) + (lane & 7)) * SROW
                      + ((seg & 1) << 3);
    }

    const int lrow = tid >> 3;     // 0..15, +16 per i
    const int lc8  = tid & 7;

    float d[4][8][4];
#pragma unroll
    for (int i = 0; i < 4; i++)
#pragma unroll
        for (int j = 0; j < 8; j++)
#pragma unroll
            for (int q = 0; q < 4; q++) d[i][j][q] = 0.0f;

    auto load_chunk = [&](int it, int s) {
        const int k0 = it * KC;
        const uint32_t aS = stage_base[s];
        const uint32_t bS = stage_base[s] + (uint32_t)(128 * SROW) * 2;
#pragma unroll
        for (int i = 0; i < 8; i++) {
            const int r = lrow + i * 16;
            CP_ASYNC16(aS + (uint32_t)(r * SROW + lc8 * 8) * 2,
                       Ag + (long long)r * D_ + k0 + lc8 * 8);
        }
#pragma unroll
        for (int i = 0; i < 8; i++) {
            const int r = lrow + i * 16;
            CP_ASYNC16(bS + (uint32_t)(r * SROW + lc8 * 8) * 2,
                       Bg + (long long)r * D_ + k0 + lc8 * 8);
        }
    };

    load_chunk(0, 0);
    CP_COMMIT();
    load_chunk(1, 1);
    CP_COMMIT();

    uint32_t a[2][4][4], b[2][4][4];

    int s = 0;
    for (int it = 0; it < NCHUNK; ++it) {
        CP_WAIT1();
        __syncthreads();

        if (it + 2 < NCHUNK) {
            int s2 = s + 2; if (s2 >= NSTAGE) s2 -= NSTAGE;
            load_chunk(it + 2, s2);
        }
        CP_COMMIT();

        const uint32_t base = stage_base[s];

#pragma unroll
        for (int am = 0; am < 4; am++)
            LDSM_X4(a[0][am], base + (uint32_t)a_off[am] * 2);
#pragma unroll
        for (int bn = 0; bn < 4; bn++)
            LDSM_X4(b[0][bn], base + (uint32_t)b_off[bn] * 2);

#pragma unroll
        for (int kk4 = 0; kk4 < 4; kk4++) {
            const int cur = kk4 & 1;
            if (kk4 < 3) {
                const int kn = (kk4 + 1) * 16;
#pragma unroll
                for (int am = 0; am < 4; am++)
                    LDSM_X4(a[cur ^ 1][am], base + (uint32_t)(a_off[am] + kn) * 2);
#pragma unroll
                for (int bn = 0; bn < 4; bn++)
                    LDSM_X4(b[cur ^ 1][bn], base + (uint32_t)(b_off[bn] + kn) * 2);
            }
#pragma unroll
            for (int am = 0; am < 4; am++)
#pragma unroll
                for (int j = 0; j < 8; j++)
                    mma_f16(d[am][j], a[cur][am], &b[cur][j >> 1][(j & 1) * 2]);
        }
        if (++s >= NSTAGE) s = 0;
    }

    // epilogue: bias + sigmoid
    const int g = lane >> 2, t4 = lane & 3;
#pragma unroll
    for (int am = 0; am < 4; am++) {
        const int r0 = row0 + wm * 64 + am * 16 + g;
#pragma unroll
        for (int j = 0; j < 8; j++) {
            const int c = col0 + wn * 64 + j * 8 + t4 * 2;
            const float bx = __ldg(bias + c), by = __ldg(bias + c + 1);
            float2 o0, o1;
            o0.x = sigmoidf_(d[am][j][0] + bx);
            o0.y = sigmoidf_(d[am][j][1] + by);
            o1.x = sigmoidf_(d[am][j][2] + bx);
            o1.y = sigmoidf_(d[am][j][3] + by);
            *(float2*)(out + (long long)r0 * D_ + c)       = o0;
            *(float2*)(out + (long long)(r0 + 8) * D_ + c) = o1;
        }
    }
}

// ---------------- launch ----------------
extern "C" void kernel_launch(void* const* d_in, const int* in_sizes, int n_in,
                              void* d_out, int out_size) {
    const float* x  = (const float*)d_in[0];
    const float* lW = (const float*)d_in[1];
    const float* lb = (const float*)d_in[2];
    const float* pW = (const float*)d_in[3];
    const float* pb = (const float*)d_in[4];
    float* out = (float*)d_out;

    prologue_kernel<<<WBLK + YBLK, 256>>>(pW, x, lW, lb);

    cudaFuncSetAttribute(gemm_mma_kernel,
                         cudaFuncAttributeMaxDynamicSharedMemorySize, SM_BYTES);
    dim3 grid(D_ / TN, B_ / TM);   // (32, 16)
    gemm_mma_kernel<<<grid, NTHR, SM_BYTES>>>(pb, out);
}